// round 1
// baseline (speedup 1.0000x reference)
#include <cuda_runtime.h>
#include <math.h>
#include <utility>

#define BATCH 32
#define D 256
#define CIN 2048
#define M 784
#define NNS 14

// ---------------- scratch (device globals; no runtime allocation) ----------
__device__ float g_Z[BATCH * D * M];        // conv output / BN-ReLU activations
__device__ float g_cov[BATCH * D * D];
__device__ float g_Y[BATCH * D * D];
__device__ float g_Zn[BATCH * D * D];
__device__ float g_T[BATCH * D * D];        // NS temp, later expm X
__device__ float g_Y2[BATCH * D * D];
__device__ float g_Z2[BATCH * D * D];
__device__ float g_E[BATCH * D * D];
__device__ float g_E2[BATCH * D * D];
__device__ float g_Sq[BATCH * D * D];       // sqrtm(cov)
__device__ float g_mu[D];
__device__ float g_rstd[D];
__device__ float g_rmean[BATCH * D];
__device__ float g_tau[BATCH];
__device__ float g_nrm[BATCH];

// ---------------- conv as batched GEMM: Z[b,d,m] = sum_c W[d,c] X[b,c,m] ----
__global__ void conv_gemm(const float* __restrict__ X, const float* __restrict__ W,
                          float* __restrict__ Z) {
    const int b  = blockIdx.z;
    const int m0 = blockIdx.x * 64;   // N dim (spatial)
    const int d0 = blockIdx.y * 64;   // M dim (out channels)
    __shared__ float As[16][64];
    __shared__ float Bs[16][68];
    const int tid = threadIdx.x;
    const int tx = tid & 15, ty = tid >> 4;
    float acc[4][4] = {};
    for (int k0 = 0; k0 < CIN; k0 += 16) {
#pragma unroll
        for (int p = 0; p < 4; ++p) {
            int dd = (tid >> 4) + p * 16;
            int kk = tid & 15;
            As[kk][dd] = W[(size_t)(d0 + dd) * CIN + k0 + kk];
        }
#pragma unroll
        for (int p = 0; p < 4; ++p) {
            int kk = (tid >> 6) + p * 4;
            int mm = tid & 63;
            int m = m0 + mm;
            Bs[kk][mm] = (m < M) ? X[((size_t)b * CIN + k0 + kk) * M + m] : 0.f;
        }
        __syncthreads();
#pragma unroll
        for (int kk = 0; kk < 16; ++kk) {
            float a[4], bb[4];
#pragma unroll
            for (int i = 0; i < 4; ++i) a[i] = As[kk][ty * 4 + i];
#pragma unroll
            for (int j = 0; j < 4; ++j) bb[j] = Bs[kk][tx * 4 + j];
#pragma unroll
            for (int i = 0; i < 4; ++i)
#pragma unroll
                for (int j = 0; j < 4; ++j) acc[i][j] = fmaf(a[i], bb[j], acc[i][j]);
        }
        __syncthreads();
    }
#pragma unroll
    for (int i = 0; i < 4; ++i) {
        int d = d0 + ty * 4 + i;
#pragma unroll
        for (int j = 0; j < 4; ++j) {
            int m = m0 + tx * 4 + j;
            if (m < M) Z[((size_t)b * D + d) * M + m] = acc[i][j];
        }
    }
}

// ---------------- BN statistics over (B, H, W) per channel -----------------
__global__ void bn_stats(const float* __restrict__ Z, float* __restrict__ mu,
                         float* __restrict__ rstd) {
    const int d = blockIdx.x;
    float s = 0.f, ss = 0.f;
    for (int idx = threadIdx.x; idx < BATCH * M; idx += blockDim.x) {
        int b = idx / M, m = idx % M;
        float v = Z[((size_t)b * D + d) * M + m];
        s += v; ss += v * v;
    }
    __shared__ float rs[256], rss[256];
    rs[threadIdx.x] = s; rss[threadIdx.x] = ss;
    __syncthreads();
    for (int o = 128; o > 0; o >>= 1) {
        if (threadIdx.x < o) { rs[threadIdx.x] += rs[threadIdx.x + o]; rss[threadIdx.x] += rss[threadIdx.x + o]; }
        __syncthreads();
    }
    if (threadIdx.x == 0) {
        const float N = (float)(BATCH * M);
        float mean = rs[0] / N;
        float var = rss[0] / N - mean * mean;
        mu[d] = mean;
        rstd[d] = rsqrtf(var + 1e-5f);
    }
}

// ---------------- BN apply + ReLU + per-(b,d) spatial mean -----------------
__global__ void bn_apply(float* __restrict__ Z, const float* __restrict__ mu,
                         const float* __restrict__ rstd, const float* __restrict__ gamma,
                         const float* __restrict__ beta, float* __restrict__ rmean) {
    const int bd = blockIdx.x;          // b*256 + d
    const int d = bd & (D - 1);
    const float mm = mu[d], r = rstd[d], g = gamma[d], be = beta[d];
    float* row = Z + (size_t)bd * M;
    float s = 0.f;
    for (int i = threadIdx.x; i < M; i += blockDim.x) {
        float v = (row[i] - mm) * r * g + be;
        v = fmaxf(v, 0.f);
        row[i] = v;
        s += v;
    }
    __shared__ float sm[128];
    sm[threadIdx.x] = s;
    __syncthreads();
    for (int o = 64; o > 0; o >>= 1) {
        if (threadIdx.x < o) sm[threadIdx.x] += sm[threadIdx.x + o];
        __syncthreads();
    }
    if (threadIdx.x == 0) rmean[bd] = sm[0] * (1.f / (float)M);
}

// ---------------- covariance: cov = Z Z^T / M - rmean rmean^T --------------
__global__ void cov_syrk(const float* __restrict__ Z, const float* __restrict__ rmean,
                         float* __restrict__ Cmat) {
    const int b = blockIdx.z;
    const float* Zb = Z + (size_t)b * D * M;
    float* Cb = Cmat + (size_t)b * D * D;
    const int n0 = blockIdx.x * 64, m0 = blockIdx.y * 64;
    __shared__ float As[16][64];
    __shared__ float Bs[16][68];
    const int tid = threadIdx.x;
    const int tx = tid & 15, ty = tid >> 4;
    float acc[4][4] = {};
    for (int k0 = 0; k0 < M; k0 += 16) {
#pragma unroll
        for (int p = 0; p < 4; ++p) {
            int mm = (tid >> 4) + p * 16;
            int kk = tid & 15;
            As[kk][mm] = Zb[(size_t)(m0 + mm) * M + k0 + kk];
            Bs[kk][mm] = Zb[(size_t)(n0 + mm) * M + k0 + kk];
        }
        __syncthreads();
#pragma unroll
        for (int kk = 0; kk < 16; ++kk) {
            float a[4], bb[4];
#pragma unroll
            for (int i = 0; i < 4; ++i) a[i] = As[kk][ty * 4 + i];
#pragma unroll
            for (int j = 0; j < 4; ++j) bb[j] = Bs[kk][tx * 4 + j];
#pragma unroll
            for (int i = 0; i < 4; ++i)
#pragma unroll
                for (int j = 0; j < 4; ++j) acc[i][j] = fmaf(a[i], bb[j], acc[i][j]);
        }
        __syncthreads();
    }
    const float invM = 1.f / (float)M;
#pragma unroll
    for (int i = 0; i < 4; ++i) {
        int m = m0 + ty * 4 + i;
#pragma unroll
        for (int j = 0; j < 4; ++j) {
            int n = n0 + tx * 4 + j;
            Cb[(size_t)m * D + n] = acc[i][j] * invM - rmean[b * D + m] * rmean[b * D + n];
        }
    }
}

// ---------------- batched 256x256x256 GEMM: C = a*A@B + beta*C + gamma*I ---
__global__ void gemm256(const float* __restrict__ A, const float* __restrict__ Bm,
                        float* __restrict__ Cmat, float alpha, float beta, float gamma) {
    const int b = blockIdx.z;
    const float* Ab = A + (size_t)b * D * D;
    const float* Bb = Bm + (size_t)b * D * D;
    float* Cb = Cmat + (size_t)b * D * D;
    const int n0 = blockIdx.x * 64, m0 = blockIdx.y * 64;
    __shared__ float As[16][64];
    __shared__ float Bs[16][68];
    const int tid = threadIdx.x;
    const int tx = tid & 15, ty = tid >> 4;
    float acc[4][4] = {};
    for (int k0 = 0; k0 < D; k0 += 16) {
#pragma unroll
        for (int p = 0; p < 4; ++p) {
            int mm = (tid >> 4) + p * 16;
            int kk = tid & 15;
            As[kk][mm] = Ab[(size_t)(m0 + mm) * D + k0 + kk];
        }
#pragma unroll
        for (int p = 0; p < 4; ++p) {
            int kk = (tid >> 6) + p * 4;
            int nn = tid & 63;
            Bs[kk][nn] = Bb[(size_t)(k0 + kk) * D + n0 + nn];
        }
        __syncthreads();
#pragma unroll
        for (int kk = 0; kk < 16; ++kk) {
            float a[4], bb[4];
#pragma unroll
            for (int i = 0; i < 4; ++i) a[i] = As[kk][ty * 4 + i];
#pragma unroll
            for (int j = 0; j < 4; ++j) bb[j] = Bs[kk][tx * 4 + j];
#pragma unroll
            for (int i = 0; i < 4; ++i)
#pragma unroll
                for (int j = 0; j < 4; ++j) acc[i][j] = fmaf(a[i], bb[j], acc[i][j]);
        }
        __syncthreads();
    }
#pragma unroll
    for (int i = 0; i < 4; ++i) {
        int m = m0 + ty * 4 + i;
#pragma unroll
        for (int j = 0; j < 4; ++j) {
            int n = n0 + tx * 4 + j;
            float v = alpha * acc[i][j];
            if (beta != 0.f) v += beta * Cb[(size_t)m * D + n];
            if (gamma != 0.f && m == n) v += gamma;
            Cb[(size_t)m * D + n] = v;
        }
    }
}

// ---------------- Frobenius norm per batch ---------------------------------
__global__ void frob_norm(const float* __restrict__ A, float* __restrict__ out) {
    const int b = blockIdx.x;
    const float* Ab = A + (size_t)b * D * D;
    float ss = 0.f;
    for (int i = threadIdx.x; i < D * D; i += 256) {
        float v = Ab[i];
        ss += v * v;
    }
    __shared__ float sm[256];
    sm[threadIdx.x] = ss;
    __syncthreads();
    for (int o = 128; o > 0; o >>= 1) {
        if (threadIdx.x < o) sm[threadIdx.x] += sm[threadIdx.x + o];
        __syncthreads();
    }
    if (threadIdx.x == 0) out[b] = fmaxf(sqrtf(sm[0]), 1e-12f);
}

// ---------------- Newton-Schulz init: Y = cov/tau, Z = I -------------------
__global__ void ns_init(const float* __restrict__ cov, const float* __restrict__ tau,
                        float* __restrict__ Y, float* __restrict__ Zi) {
    const int b = blockIdx.y, i = blockIdx.x;
    const float it = 1.f / tau[b];
    const size_t off = ((size_t)b * D + i) * D;
    for (int j = threadIdx.x; j < D; j += blockDim.x) {
        Y[off + j] = cov[off + j] * it;
        Zi[off + j] = (i == j) ? 1.f : 0.f;
    }
}

// ---------------- rescale: Sq = sqrt(tau)*Y --------------------------------
__global__ void scale_sqrt(const float* __restrict__ Y, const float* __restrict__ tau,
                           float* __restrict__ Sq) {
    const int b = blockIdx.y, i = blockIdx.x;
    const float s = sqrtf(tau[b]);
    const size_t off = ((size_t)b * D + i) * D;
    for (int j = threadIdx.x; j < D; j += blockDim.x) Sq[off + j] = Y[off + j] * s;
}

// ---------------- expm init: X = -cov/64, E = I + X/8 ----------------------
__global__ void expm_init(const float* __restrict__ cov, float* __restrict__ X,
                          float* __restrict__ E) {
    const int b = blockIdx.y, i = blockIdx.x;
    const size_t off = ((size_t)b * D + i) * D;
    for (int j = threadIdx.x; j < D; j += blockDim.x) {
        float x = cov[off + j] * (-1.f / 64.f);
        X[off + j] = x;
        E[off + j] = x * 0.125f + ((i == j) ? 1.f : 0.f);
    }
}

// ---------------- output: y = (1 + ||Sq@E||_F) * Sq, upper triangle --------
__global__ void out_triu(const float* __restrict__ Sq, const float* __restrict__ nrm,
                         float* __restrict__ out) {
    const int b = blockIdx.y, i = blockIdx.x;
    const float sc = 1.f + nrm[b];
    const size_t rowoff = (size_t)i * D - (size_t)i * (i - 1) / 2;
    const float* row = Sq + ((size_t)b * D + i) * D;
    float* ob = out + (size_t)b * (D * (D + 1) / 2) + rowoff - i;
    for (int j = i + (int)threadIdx.x; j < D; j += blockDim.x) ob[j] = sc * row[j];
}

// ---------------------------------------------------------------------------
static float* sym_addr(const void* symbol) {
    void* p = nullptr;
    cudaGetSymbolAddress(&p, symbol);
    return (float*)p;
}

extern "C" void kernel_launch(void* const* d_in, const int* in_sizes, int n_in,
                              void* d_out, int out_size) {
    const float* x  = (const float*)d_in[0];
    const float* w  = (const float*)d_in[1];
    const float* gm = (const float*)d_in[2];
    const float* bt = (const float*)d_in[3];
    float* out = (float*)d_out;

    float* Z    = sym_addr(g_Z);
    float* cov  = sym_addr(g_cov);
    float* Y    = sym_addr(g_Y);
    float* Zw   = sym_addr(g_Zn);
    float* T    = sym_addr(g_T);
    float* Y2   = sym_addr(g_Y2);
    float* Z2   = sym_addr(g_Z2);
    float* E    = sym_addr(g_E);
    float* E2   = sym_addr(g_E2);
    float* Sq   = sym_addr(g_Sq);
    float* mu   = sym_addr(g_mu);
    float* rstd = sym_addr(g_rstd);
    float* rmn  = sym_addr(g_rmean);
    float* tau  = sym_addr(g_tau);
    float* nrm  = sym_addr(g_nrm);

    // 1. conv 1x1 as batched GEMM
    conv_gemm<<<dim3(13, 4, BATCH), 256>>>(x, w, Z);
    // 2. BN stats
    bn_stats<<<D, 256>>>(Z, mu, rstd);
    // 3. BN apply + ReLU + row means
    bn_apply<<<BATCH * D, 128>>>(Z, mu, rstd, gm, bt, rmn);
    // 4. covariance
    cov_syrk<<<dim3(4, 4, BATCH), 256>>>(Z, rmn, cov);
    // 5. normalization scale (Frobenius >= spectral norm)
    frob_norm<<<BATCH, 256>>>(cov, tau);
    // 6. coupled Newton-Schulz for sqrtm
    ns_init<<<dim3(D, BATCH), 256>>>(cov, tau, Y, Zw);
    const dim3 gg(4, 4, BATCH);
    float *Yc = Y, *Zc = Zw, *Yn = Y2, *Zn = Z2;
    for (int it = 0; it < NNS; ++it) {
        gemm256<<<gg, 256>>>(Zc, Yc, T, -1.f, 0.f, 3.f);     // T = 3I - Z@Y
        gemm256<<<gg, 256>>>(Yc, T, Yn, 0.5f, 0.f, 0.f);     // Y' = Y@T/2
        gemm256<<<gg, 256>>>(T, Zc, Zn, 0.5f, 0.f, 0.f);     // Z' = T@Z/2
        std::swap(Yc, Yn); std::swap(Zc, Zn);
    }
    // 7. sqrtm(cov) = sqrt(tau) * Y
    scale_sqrt<<<dim3(D, BATCH), 256>>>(Yc, tau, Sq);
    // 8. expm(-cov): scaling & squaring, Taylor-8, S=6
    expm_init<<<dim3(D, BATCH), 256>>>(cov, T, E);           // T=X=-cov/64, E=I+X/8
    float *Ec = E, *En = E2;
    for (int k = 7; k >= 1; --k) {
        gemm256<<<gg, 256>>>(T, Ec, En, 1.f / (float)k, 0.f, 1.f);  // E = I + X@E/k
        std::swap(Ec, En);
    }
    for (int sq = 0; sq < 6; ++sq) {
        gemm256<<<gg, 256>>>(Ec, Ec, En, 1.f, 0.f, 0.f);     // E = E@E
        std::swap(Ec, En);
    }
    // 9. P = Sq @ E  (reuse Z scratch), nrm = ||P||_F
    gemm256<<<gg, 256>>>(Sq, Ec, Z, 1.f, 0.f, 0.f);
    frob_norm<<<BATCH, 256>>>(Z, nrm);
    // 10. y = (1+nrm)*Sq, extract upper triangle
    out_triu<<<dim3(D, BATCH), 256>>>(Sq, nrm, out);

    (void)in_sizes; (void)n_in; (void)out_size;
}

// round 2
// speedup vs baseline: 1.6813x; 1.6813x over previous
#include <cuda_runtime.h>
#include <math.h>
#include <utility>

#define BATCH 32
#define D 256
#define CIN 2048
#define M 784
#define NNS 11
#define NPOW 10

#define BM 128
#define BN 128
#define BK 8

typedef unsigned long long ull;

// ---------------- scratch (device globals) ---------------------------------
__device__ float g_Z[BATCH * D * M];        // conv output / BN-ReLU acts / P
__device__ float g_cov[BATCH * D * D];
__device__ float g_Y[BATCH * D * D];        // Anorm -> Y ping
__device__ float g_Y2[BATCH * D * D];
__device__ float g_Zm[BATCH * D * D];       // Z ping
__device__ float g_Z2[BATCH * D * D];
__device__ float g_T[BATCH * D * D];        // A^2 / T / X
__device__ float g_E[BATCH * D * D];
__device__ float g_E2[BATCH * D * D];
__device__ float g_Sq[BATCH * D * D];
__device__ float g_mu[D];
__device__ float g_rstd[D];
__device__ float g_rmean[BATCH * D];
__device__ float g_tau[BATCH];
__device__ float g_stau[BATCH];
__device__ float g_nrm[BATCH];

// ---------------- packed f32x2 FMA -----------------------------------------
__device__ __forceinline__ void ffma2(ull &c, ull a, ull b) {
    asm("fma.rn.f32x2 %0, %1, %2, %0;" : "+l"(c) : "l"(a), "l"(b));
}
__device__ __forceinline__ float2 u2f(ull u) {
    float2 f; asm("mov.b64 {%0, %1}, %2;" : "=f"(f.x), "=f"(f.y) : "l"(u)); return f;
}

// ---------------------------------------------------------------------------
// Unified SGEMM: C[z] = alpha*(A[z] @ opB(B[z])) [+ gamma*I] [cov-epilogue]
// Mdim fixed = 256 (grid.y = 2). TRANSB: Bs[k][n] = B[n][k]. EPI: 0 plain, 1 cov.
// alphaDev: optional per-batch multiplier on alpha.
// ---------------------------------------------------------------------------
template<int TRANSB, int EPI>
__global__ __launch_bounds__(256, 2)
void sgemm_f32x2(const float* __restrict__ A, const float* __restrict__ B,
                 float* __restrict__ C,
                 int Ndim, int K, int lda, int ldb, int ldc,
                 long long sA, long long sB, long long sC,
                 float alpha, float gamma,
                 const float* __restrict__ alphaDev,
                 const float* __restrict__ rmean) {
    __shared__ float2 As2s[2 * BK * BM];   // duplicated A: As2[k][m] = {a,a}
    __shared__ float  Bss[2 * BK * BN];

    const int t  = threadIdx.x;
    const int tx = t & 15;
    const int ty = t >> 4;
    const int z  = blockIdx.z;
    const int n0 = blockIdx.x * BN;
    const int m0 = blockIdx.y * BM;

    const float* Ag = A + (long long)z * sA + (size_t)(m0 + (t >> 1)) * lda + ((t & 1) << 2);
    const float* Bg;
    bool nOK = true;
    if (TRANSB == 0) {
        int nB = (t & 31) << 2;
        nOK = (n0 + nB) < Ndim;
        Bg = B + (long long)z * sB + (size_t)(t >> 5) * ldb + n0 + nB;
    } else {
        Bg = B + (long long)z * sB + (size_t)(n0 + (t >> 1)) * ldb + ((t & 1) << 2);
    }

    const float4 f4z = make_float4(0.f, 0.f, 0.f, 0.f);
    float4 aReg = *(const float4*)Ag;
    float4 bReg = (TRANSB == 0 && !nOK) ? f4z : *(const float4*)Bg;

    ull acc[8][4];
#pragma unroll
    for (int i = 0; i < 8; ++i)
#pragma unroll
        for (int j = 0; j < 4; ++j) acc[i][j] = 0ULL;

    const int PNL = K / BK;

    // STS panel 0
    {
        float av[4] = {aReg.x, aReg.y, aReg.z, aReg.w};
#pragma unroll
        for (int j = 0; j < 4; ++j)
            As2s[(4 * (t & 1) + j) * BM + (t >> 1)] = make_float2(av[j], av[j]);
        if (TRANSB == 0) {
            *(float4*)&Bss[(t >> 5) * BN + ((t & 31) << 2)] = bReg;
        } else {
            float bv[4] = {bReg.x, bReg.y, bReg.z, bReg.w};
#pragma unroll
            for (int j = 0; j < 4; ++j)
                Bss[(4 * (t & 1) + j) * BN + (t >> 1)] = bv[j];
        }
    }
    __syncthreads();

    for (int p = 0; p < PNL; ++p) {
        const int buf = p & 1;
        if (p + 1 < PNL) {
            aReg = *(const float4*)(Ag + (size_t)(p + 1) * BK);
            if (TRANSB == 0)
                bReg = nOK ? *(const float4*)(Bg + (size_t)(p + 1) * BK * ldb) : f4z;
            else
                bReg = *(const float4*)(Bg + (size_t)(p + 1) * BK);
        }
        // compute
        const float2* Ak = As2s + buf * BK * BM;
        const float*  Bk = Bss + buf * BK * BN;
#pragma unroll
        for (int k = 0; k < BK; ++k) {
            const float2* Ar = Ak + k * BM;
            const float*  Br = Bk + k * BN;
            ulonglong2 A0 = *(const ulonglong2*)(Ar + ty * 4);
            ulonglong2 A1 = *(const ulonglong2*)(Ar + ty * 4 + 2);
            ulonglong2 A2 = *(const ulonglong2*)(Ar + ty * 4 + 64);
            ulonglong2 A3 = *(const ulonglong2*)(Ar + ty * 4 + 66);
            ulonglong2 B0 = *(const ulonglong2*)(Br + tx * 4);
            ulonglong2 B1 = *(const ulonglong2*)(Br + tx * 4 + 64);
            ull ad[8] = {A0.x, A0.y, A1.x, A1.y, A2.x, A2.y, A3.x, A3.y};
            ull bp[4] = {B0.x, B0.y, B1.x, B1.y};
#pragma unroll
            for (int i = 0; i < 8; ++i)
#pragma unroll
                for (int j = 0; j < 4; ++j) ffma2(acc[i][j], ad[i], bp[j]);
        }
        if (p + 1 < PNL) {
            float av[4] = {aReg.x, aReg.y, aReg.z, aReg.w};
            const int nb = buf ^ 1;
#pragma unroll
            for (int j = 0; j < 4; ++j)
                As2s[(nb * BK + 4 * (t & 1) + j) * BM + (t >> 1)] = make_float2(av[j], av[j]);
            if (TRANSB == 0) {
                *(float4*)&Bss[(nb * BK + (t >> 5)) * BN + ((t & 31) << 2)] = bReg;
            } else {
                float bv[4] = {bReg.x, bReg.y, bReg.z, bReg.w};
#pragma unroll
                for (int j = 0; j < 4; ++j)
                    Bss[(nb * BK + 4 * (t & 1) + j) * BN + (t >> 1)] = bv[j];
            }
        }
        __syncthreads();
    }

    // epilogue
    const float aeff = alpha * (alphaDev ? alphaDev[z] : 1.f);
    float* Cb = C + (long long)z * sC;
#pragma unroll
    for (int i = 0; i < 8; ++i) {
        const int m = m0 + ((i < 4) ? ty * 4 + i : 64 + ty * 4 + (i - 4));
        float rm;
        if (EPI == 1) rm = rmean[z * D + m];
#pragma unroll
        for (int half = 0; half < 2; ++half) {
            const int n = n0 + half * 64 + tx * 4;
            if (n >= Ndim) continue;
            float2 lo = u2f(acc[i][half * 2]);
            float2 hi = u2f(acc[i][half * 2 + 1]);
            float4 o = make_float4(aeff * lo.x, aeff * lo.y, aeff * hi.x, aeff * hi.y);
            if (EPI == 1) {
                o.x -= rm * rmean[z * D + n + 0];
                o.y -= rm * rmean[z * D + n + 1];
                o.z -= rm * rmean[z * D + n + 2];
                o.w -= rm * rmean[z * D + n + 3];
            } else if (gamma != 0.f) {
                if (m == n + 0) o.x += gamma;
                if (m == n + 1) o.y += gamma;
                if (m == n + 2) o.z += gamma;
                if (m == n + 3) o.w += gamma;
            }
            *(float4*)&Cb[(size_t)m * ldc + n] = o;
        }
    }
}

// ---------------- BN statistics --------------------------------------------
__global__ void bn_stats(const float* __restrict__ Z, float* __restrict__ mu,
                         float* __restrict__ rstd) {
    const int d = blockIdx.x;
    float s = 0.f, ss = 0.f;
    for (int idx = threadIdx.x; idx < BATCH * M; idx += blockDim.x) {
        int b = idx / M, m = idx % M;
        float v = Z[((size_t)b * D + d) * M + m];
        s += v; ss += v * v;
    }
    __shared__ float rs[256], rss[256];
    rs[threadIdx.x] = s; rss[threadIdx.x] = ss;
    __syncthreads();
    for (int o = 128; o > 0; o >>= 1) {
        if (threadIdx.x < o) { rs[threadIdx.x] += rs[threadIdx.x + o]; rss[threadIdx.x] += rss[threadIdx.x + o]; }
        __syncthreads();
    }
    if (threadIdx.x == 0) {
        const float N = (float)(BATCH * M);
        float mean = rs[0] / N;
        float var = rss[0] / N - mean * mean;
        mu[d] = mean;
        rstd[d] = rsqrtf(var + 1e-5f);
    }
}

// ---------------- BN apply + ReLU + row mean -------------------------------
__global__ void bn_apply(float* __restrict__ Z, const float* __restrict__ mu,
                         const float* __restrict__ rstd, const float* __restrict__ gamma,
                         const float* __restrict__ beta, float* __restrict__ rmean) {
    const int bd = blockIdx.x;
    const int d = bd & (D - 1);
    const float mm = mu[d], r = rstd[d], g = gamma[d], be = beta[d];
    float* row = Z + (size_t)bd * M;
    float s = 0.f;
    for (int i = threadIdx.x; i < M; i += blockDim.x) {
        float v = (row[i] - mm) * r * g + be;
        v = fmaxf(v, 0.f);
        row[i] = v;
        s += v;
    }
    __shared__ float sm[128];
    sm[threadIdx.x] = s;
    __syncthreads();
    for (int o = 64; o > 0; o >>= 1) {
        if (threadIdx.x < o) sm[threadIdx.x] += sm[threadIdx.x + o];
        __syncthreads();
    }
    if (threadIdx.x == 0) rmean[bd] = sm[0] * (1.f / (float)M);
}

// ---------------- power iteration: tau ~= lambda_max -----------------------
__global__ void power_iter(const float* __restrict__ cov, float* __restrict__ tau,
                           float* __restrict__ stau) {
    const int b = blockIdx.x;
    const float* Cb = cov + (size_t)b * D * D;
    __shared__ float v[D];
    __shared__ float red[256];
    const int t = threadIdx.x;
    v[t] = 1.f;
    __syncthreads();
    float lam = 1.f;
    for (int it = 0; it < NPOW; ++it) {
        float w = 0.f;
#pragma unroll 4
        for (int j = 0; j < D; ++j) w = fmaf(Cb[(size_t)j * D + t], v[j], w);
        red[t] = w * w;
        __syncthreads();
        for (int o = 128; o > 0; o >>= 1) {
            if (t < o) red[t] += red[t + o];
            __syncthreads();
        }
        lam = sqrtf(red[0]);
        v[t] = w / fmaxf(lam, 1e-20f);
        __syncthreads();
    }
    if (t == 0) {
        float l = fmaxf(lam, 1e-12f);
        tau[b] = l;
        stau[b] = sqrtf(l);
    }
}

// ---------------- Anorm = cov / tau ----------------------------------------
__global__ void ns_init(const float* __restrict__ cov, const float* __restrict__ tau,
                        float* __restrict__ An) {
    const int b = blockIdx.y, i = blockIdx.x;
    const float it = 1.f / tau[b];
    const size_t off = ((size_t)b * D + i) * D;
    for (int j = threadIdx.x; j < D; j += blockDim.x) An[off + j] = cov[off + j] * it;
}

// ---------------- first NS iteration (in-place A->Y; Z from A) -------------
__global__ void ns_first(float* __restrict__ A, const float* __restrict__ S,
                         float* __restrict__ Zo) {
    const int b = blockIdx.y, i = blockIdx.x;
    const size_t off = ((size_t)b * D + i) * D;
    for (int j = threadIdx.x; j < D; j += blockDim.x) {
        float a = A[off + j];
        A[off + j]  = 1.5f * a - 0.5f * S[off + j];
        Zo[off + j] = -0.5f * a + ((i == j) ? 1.5f : 0.f);
    }
}

// ---------------- expm init: X = -cov/64, E = I + X/5 ----------------------
__global__ void expm_init(const float* __restrict__ cov, float* __restrict__ X,
                          float* __restrict__ E) {
    const int b = blockIdx.y, i = blockIdx.x;
    const size_t off = ((size_t)b * D + i) * D;
    for (int j = threadIdx.x; j < D; j += blockDim.x) {
        float x = cov[off + j] * (-1.f / 64.f);
        X[off + j] = x;
        E[off + j] = 0.2f * x + ((i == j) ? 1.f : 0.f);
    }
}

// ---------------- Frobenius norm per batch ---------------------------------
__global__ void frob_norm(const float* __restrict__ A, float* __restrict__ out) {
    const int b = blockIdx.x;
    const float* Ab = A + (size_t)b * D * D;
    float ss = 0.f;
    for (int i = threadIdx.x; i < D * D; i += 256) {
        float v = Ab[i];
        ss += v * v;
    }
    __shared__ float sm[256];
    sm[threadIdx.x] = ss;
    __syncthreads();
    for (int o = 128; o > 0; o >>= 1) {
        if (threadIdx.x < o) sm[threadIdx.x] += sm[threadIdx.x + o];
        __syncthreads();
    }
    if (threadIdx.x == 0) out[b] = fmaxf(sqrtf(sm[0]), 1e-12f);
}

// ---------------- output: y = (1 + nrm[b]) * Sq, upper triangle ------------
__global__ void out_triu(const float* __restrict__ Sq, const float* __restrict__ nrm,
                         float* __restrict__ out) {
    const int b = blockIdx.y, i = blockIdx.x;
    const float sc = 1.f + nrm[b];
    const size_t rowoff = (size_t)i * D - (size_t)i * (i - 1) / 2;
    const float* row = Sq + ((size_t)b * D + i) * D;
    float* ob = out + (size_t)b * (D * (D + 1) / 2) + rowoff - i;
    for (int j = i + (int)threadIdx.x; j < D; j += blockDim.x) ob[j] = sc * row[j];
}

// ---------------------------------------------------------------------------
static float* sym_addr(const void* symbol) {
    void* p = nullptr;
    cudaGetSymbolAddress(&p, symbol);
    return (float*)p;
}

extern "C" void kernel_launch(void* const* d_in, const int* in_sizes, int n_in,
                              void* d_out, int out_size) {
    const float* x  = (const float*)d_in[0];
    const float* w  = (const float*)d_in[1];
    const float* gm = (const float*)d_in[2];
    const float* bt = (const float*)d_in[3];
    float* out = (float*)d_out;

    float* Z    = sym_addr(g_Z);
    float* cov  = sym_addr(g_cov);
    float* Y    = sym_addr(g_Y);
    float* Y2   = sym_addr(g_Y2);
    float* Zm   = sym_addr(g_Zm);
    float* Z2   = sym_addr(g_Z2);
    float* T    = sym_addr(g_T);
    float* E    = sym_addr(g_E);
    float* E2   = sym_addr(g_E2);
    float* Sq   = sym_addr(g_Sq);
    float* mu   = sym_addr(g_mu);
    float* rstd = sym_addr(g_rstd);
    float* rmn  = sym_addr(g_rmean);
    float* tau  = sym_addr(g_tau);
    float* stau = sym_addr(g_stau);
    float* nrm  = sym_addr(g_nrm);

    const long long DM = (long long)D * M;       // 200704
    const long long DD = (long long)D * D;       // 65536
    const dim3 gConv(7, 2, BATCH);
    const dim3 gSq(2, 2, BATCH);

    // 1. conv 1x1: Z[b,d,m] = sum_c W[d,c] X[b,c,m]
    sgemm_f32x2<0, 0><<<gConv, 256>>>(w, x, Z, M, CIN, CIN, M, M,
                                      0LL, (long long)CIN * M, DM,
                                      1.f, 0.f, nullptr, nullptr);
    // 2-3. BN
    bn_stats<<<D, 256>>>(Z, mu, rstd);
    bn_apply<<<BATCH * D, 128>>>(Z, mu, rstd, gm, bt, rmn);
    // 4. covariance: cov = Z Z^T / M - rmean rmean^T
    sgemm_f32x2<1, 1><<<gSq, 256>>>(Z, Z, cov, D, M, M, M, D,
                                    DM, DM, DD,
                                    1.f / (float)M, 0.f, nullptr, rmn);
    // 5. spectral norm estimate
    power_iter<<<BATCH, 256>>>(cov, tau, stau);
    // 6. Newton-Schulz for sqrtm
    ns_init<<<dim3(D, BATCH), 256>>>(cov, tau, Y);
    sgemm_f32x2<0, 0><<<gSq, 256>>>(Y, Y, T, D, D, D, D, D, DD, DD, DD,
                                    1.f, 0.f, nullptr, nullptr);          // T = A^2
    ns_first<<<dim3(D, BATCH), 256>>>(Y, T, Zm);                          // Y1, Z1
    float *Yc = Y, *Zc = Zm, *Yn = Y2, *Zn = Z2;
    for (int it = 2; it <= NNS; ++it) {
        sgemm_f32x2<0, 0><<<gSq, 256>>>(Zc, Yc, T, D, D, D, D, D, DD, DD, DD,
                                        -1.f, 3.f, nullptr, nullptr);     // T = 3I - Z@Y
        if (it < NNS) {
            sgemm_f32x2<0, 0><<<gSq, 256>>>(Yc, T, Yn, D, D, D, D, D, DD, DD, DD,
                                            0.5f, 0.f, nullptr, nullptr); // Y' = Y@T/2
            sgemm_f32x2<0, 0><<<gSq, 256>>>(T, Zc, Zn, D, D, D, D, D, DD, DD, DD,
                                            0.5f, 0.f, nullptr, nullptr); // Z' = T@Z/2
            std::swap(Yc, Yn); std::swap(Zc, Zn);
        } else {
            // final: Sq = sqrt(tau) * Y@T/2
            sgemm_f32x2<0, 0><<<gSq, 256>>>(Yc, T, Sq, D, D, D, D, D, DD, DD, DD,
                                            0.5f, 0.f, stau, nullptr);
        }
    }
    // 7. expm(-cov): Taylor-5 + 6 squarings
    expm_init<<<dim3(D, BATCH), 256>>>(cov, T, E);                        // T = X
    float *Ec = E, *En = E2;
    for (int k = 4; k >= 1; --k) {
        sgemm_f32x2<0, 0><<<gSq, 256>>>(T, Ec, En, D, D, D, D, D, DD, DD, DD,
                                        1.f / (float)k, 1.f, nullptr, nullptr);
        std::swap(Ec, En);
    }
    for (int sq = 0; sq < 6; ++sq) {
        sgemm_f32x2<0, 0><<<gSq, 256>>>(Ec, Ec, En, D, D, D, D, D, DD, DD, DD,
                                        1.f, 0.f, nullptr, nullptr);
        std::swap(Ec, En);
    }
    // 8. P = Sq @ E, nrm = ||P||_F
    sgemm_f32x2<0, 0><<<gSq, 256>>>(Sq, Ec, Z, D, D, D, D, D, DD, DD, DD,
                                    1.f, 0.f, nullptr, nullptr);
    frob_norm<<<BATCH, 256>>>(Z, nrm);
    // 9. output
    out_triu<<<dim3(D, BATCH), 256>>>(Sq, nrm, out);

    (void)in_sizes; (void)n_in; (void)out_size;
}